// round 2
// baseline (speedup 1.0000x reference)
#include <cuda_runtime.h>

#define B_   4
#define T_   2048
#define HIN_ 1024
#define H_   16
#define E_   64
#define HE_  (H_ * E_)   // 1024
#define BT_  (B_ * T_)   // 8192

// Persistent scratch (no allocations allowed in kernel_launch).
__device__ float g_Q[BT_ * HE_];
__device__ float g_K[BT_ * HE_];
__device__ float g_V[BT_ * HE_];

// ---------------------------------------------------------------------------
// Projection GEMM: C[M=8192, N=1024] = A[M, K=1024] @ W[K, N], C *= scale
// 64x64 CTA tile, BK=16, 256 threads, 4x4 micro-tile per thread.
// sel: 0 -> g_Q, 1 -> g_K, 2 -> g_V (avoids host-side symbol lookups).
// ---------------------------------------------------------------------------
__global__ __launch_bounds__(256) void proj_gemm(const float* __restrict__ A,
                                                 const float* __restrict__ W,
                                                 int sel, float scale) {
    __shared__ float AsT[16][64];   // A tile transposed: [k][m]
    __shared__ float Ws[16][64];    // W tile natural:    [k][n]

    float* __restrict__ C = (sel == 0) ? g_Q : (sel == 1) ? g_K : g_V;

    const int tid = threadIdx.x;
    const int ty = tid >> 4;          // 0..15 (q-row group)
    const int tx = tid & 15;          // 0..15 (col group)
    const int bm = blockIdx.y << 6;
    const int bn = blockIdx.x << 6;

    // A loader: 64 rows x 16 cols, one float4 per thread
    const int ar = tid >> 2;              // 0..63
    const int ac = (tid & 3) << 2;        // 0,4,8,12
    // W loader: 16 rows x 64 cols, one float4 per thread
    const int wr = tid >> 4;              // 0..15
    const int wc = (tid & 15) << 2;       // 0..60

    const float* Ap = A + (size_t)(bm + ar) * HIN_ + ac;
    const float* Wp = W + (size_t)wr * HE_ + bn + wc;

    float acc[4][4] = {};

    for (int k0 = 0; k0 < HIN_; k0 += 16) {
        float4 av = *(const float4*)(Ap + k0);
        float4 wv = *(const float4*)(Wp + (size_t)k0 * HE_);
        __syncthreads();   // previous iteration done reading smem
        AsT[ac + 0][ar] = av.x;
        AsT[ac + 1][ar] = av.y;
        AsT[ac + 2][ar] = av.z;
        AsT[ac + 3][ar] = av.w;
        *(float4*)&Ws[wr][wc] = wv;
        __syncthreads();

#pragma unroll
        for (int kk = 0; kk < 16; kk++) {
            float4 a4 = *(const float4*)&AsT[kk][ty << 2];   // broadcast across tx
            float4 w4 = *(const float4*)&Ws[kk][tx << 2];    // conflict-free span
            float a[4] = {a4.x, a4.y, a4.z, a4.w};
            float w[4] = {w4.x, w4.y, w4.z, w4.w};
#pragma unroll
            for (int i = 0; i < 4; i++)
#pragma unroll
                for (int j = 0; j < 4; j++) acc[i][j] += a[i] * w[j];
        }
    }

#pragma unroll
    for (int i = 0; i < 4; i++) {
        float4 r = make_float4(acc[i][0] * scale, acc[i][1] * scale,
                               acc[i][2] * scale, acc[i][3] * scale);
        *(float4*)&C[(size_t)(bm + (ty << 2) + i) * HE_ + bn + (tx << 2)] = r;
    }
}

// ---------------------------------------------------------------------------
// Flash attention: one CTA = 64 query rows for a fixed (b, h).
// Iterates 32 key tiles of 64; online softmax; KsT buffer reused for P.
// Q and K already carry the E^-0.25 scale from the projection.
// ---------------------------------------------------------------------------
__global__ __launch_bounds__(256) void flash_attn(float* __restrict__ Out) {
    __shared__ float QsT[64][64];   // [e][qrow]
    __shared__ float KsT[64][64];   // [e][krow], reused as P[qrow][krow]
    __shared__ float Vs[64][64];    // [krow][e]

    const int tid = threadIdx.x;
    const int ty = tid >> 4;        // q-row group 0..15
    const int tx = tid & 15;        // col group 0..15
    const int q0 = blockIdx.x << 6;
    const int h  = blockIdx.y;
    const int b  = blockIdx.z;

    const size_t baseQ  = ((size_t)(b * T_ + q0) * H_ + h) * E_;
    const size_t baseKV = ((size_t)b * T_ * H_ + h) * E_;

    // Load Q tile transposed (once per CTA)
    for (int idx = tid; idx < 1024; idx += 256) {
        int row = idx >> 4;
        int c = (idx & 15) << 2;
        float4 v = *(const float4*)(g_Q + baseQ + (size_t)row * HE_ + c);
        QsT[c + 0][row] = v.x;
        QsT[c + 1][row] = v.y;
        QsT[c + 2][row] = v.z;
        QsT[c + 3][row] = v.w;
    }

    float m[4], l[4], o[4][4];
#pragma unroll
    for (int i = 0; i < 4; i++) {
        m[i] = -1e30f;
        l[i] = 0.f;
#pragma unroll
        for (int j = 0; j < 4; j++) o[i][j] = 0.f;
    }

    for (int k0 = 0; k0 < T_; k0 += 64) {
        __syncthreads();   // prior tile done with KsT/Vs (and Q load visible)
        for (int idx = tid; idx < 1024; idx += 256) {
            int row = idx >> 4;
            int c = (idx & 15) << 2;
            size_t g = baseKV + (size_t)(k0 + row) * HE_ + c;
            float4 kv = *(const float4*)(g_K + g);
            KsT[c + 0][row] = kv.x;
            KsT[c + 1][row] = kv.y;
            KsT[c + 2][row] = kv.z;
            KsT[c + 3][row] = kv.w;
            *(float4*)&Vs[row][c] = *(const float4*)(g_V + g);
        }
        __syncthreads();

        // S = Q K^T (outer products over e)
        float s[4][4] = {};
#pragma unroll 16
        for (int e = 0; e < 64; e++) {
            float4 q4 = *(const float4*)&QsT[e][ty << 2];
            float4 k4 = *(const float4*)&KsT[e][tx << 2];
            float q[4] = {q4.x, q4.y, q4.z, q4.w};
            float k[4] = {k4.x, k4.y, k4.z, k4.w};
#pragma unroll
            for (int i = 0; i < 4; i++)
#pragma unroll
                for (int j = 0; j < 4; j++) s[i][j] += q[i] * k[j];
        }

        // Online softmax (reduce across the 16 tx lanes sharing each q row)
#pragma unroll
        for (int i = 0; i < 4; i++) {
            float mx = fmaxf(fmaxf(s[i][0], s[i][1]), fmaxf(s[i][2], s[i][3]));
#pragma unroll
            for (int off = 8; off >= 1; off >>= 1)
                mx = fmaxf(mx, __shfl_xor_sync(0xffffffffu, mx, off));
            float mnew = fmaxf(m[i], mx);
            float corr = __expf(m[i] - mnew);
            float rs = 0.f;
#pragma unroll
            for (int j = 0; j < 4; j++) {
                s[i][j] = __expf(s[i][j] - mnew);
                rs += s[i][j];
            }
#pragma unroll
            for (int off = 8; off >= 1; off >>= 1)
                rs += __shfl_xor_sync(0xffffffffu, rs, off);
            l[i] = l[i] * corr + rs;
            m[i] = mnew;
#pragma unroll
            for (int j = 0; j < 4; j++) o[i][j] *= corr;
        }

        __syncthreads();   // everyone done reading KsT as K
#pragma unroll
        for (int i = 0; i < 4; i++)
            *(float4*)&KsT[(ty << 2) + i][tx << 2] =
                make_float4(s[i][0], s[i][1], s[i][2], s[i][3]);
        __syncthreads();   // P visible

        // O += P @ V
#pragma unroll 16
        for (int k = 0; k < 64; k++) {
            float4 v4 = *(const float4*)&Vs[k][tx << 2];
            float vv[4] = {v4.x, v4.y, v4.z, v4.w};
#pragma unroll
            for (int i = 0; i < 4; i++) {
                float p = KsT[(ty << 2) + i][k];   // broadcast across tx
#pragma unroll
                for (int j = 0; j < 4; j++) o[i][j] += p * vv[j];
            }
        }
    }

#pragma unroll
    for (int i = 0; i < 4; i++) {
        float inv = 1.0f / l[i];
        float4 r = make_float4(o[i][0] * inv, o[i][1] * inv,
                               o[i][2] * inv, o[i][3] * inv);
        *(float4*)&Out[((size_t)(b * T_ + q0 + (ty << 2) + i) * H_ + h) * E_ +
                       (tx << 2)] = r;
    }
}

// ---------------------------------------------------------------------------
extern "C" void kernel_launch(void* const* d_in, const int* in_sizes, int n_in,
                              void* d_out, int out_size) {
    const float* query     = (const float*)d_in[0];
    const float* key_value = (const float*)d_in[1];
    const float* Wq        = (const float*)d_in[2];
    const float* Wk        = (const float*)d_in[3];
    const float* Wv        = (const float*)d_in[4];
    float* out = (float*)d_out;

    const float scale = 0.35355339059327379f;  // 64^(-1/4)

    dim3 gproj(HE_ / 64, BT_ / 64);            // (16, 128)
    proj_gemm<<<gproj, 256>>>(query,     Wq, 0, scale);
    proj_gemm<<<gproj, 256>>>(key_value, Wk, 1, scale);
    proj_gemm<<<gproj, 256>>>(key_value, Wv, 2, 1.0f);

    dim3 gattn(T_ / 64, H_, B_);               // (32, 16, 4)
    flash_attn<<<gattn, 256>>>(out);
}